// round 4
// baseline (speedup 1.0000x reference)
#include <cuda_runtime.h>

// Focal cross-entropy, N rows x 2 classes, scalar-sum output. Single kernel:
// 8 rows/thread, int32 indexing, block reduce -> double atomicAdd -> fenced
// last-block writes out & resets state (graph-replay safe).
// inputs: d_in[0] = pred [N,2] f32, d_in[1] = gold [N] f32. out: 1 f32.

__device__ double g_acc = 0.0;
__device__ unsigned int g_done = 0u;

__device__ __forceinline__ float row_loss(float p0, float p1, float g) {
    // 2-class identity: d = p1-p0, t = exp(-|d|), L = log(1+t)
    //   -lp(hi)=L, -lp(lo)=|d|+L ; prb(hi)=1/(1+t), prb(lo)=t/(1+t)
    //   focal_c = prb_other^2
    float d   = p1 - p0;
    float ad  = fabsf(d);
    float t   = __expf(-ad);                 // MUFU.EX2
    float s   = 1.0f + t;
    float L   = __logf(s);                   // MUFU.LG2
    float inv = __fdividef(1.0f, s);         // MUFU.RCP
    float pr_hi = inv;
    float pr_lo = t * inv;

    bool pos = (d >= 0.0f);
    float nlp0 = pos ? (ad + L) : L;         // -log_softmax[0]
    float nlp1 = pos ? L : (ad + L);         // -log_softmax[1]
    float pr0  = pos ? pr_lo : pr_hi;
    float pr1  = pos ? pr_hi : pr_lo;

    float oh1 = (g >= 0.5f) ? 0.25f : 0.0f;
    float oh0 = (1.0f - oh1) * 0.75f;

    return oh0 * nlp0 * (pr1 * pr1) + oh1 * nlp1 * (pr0 * pr0);
}

__global__ void __launch_bounds__(256)
fl_fused_kernel(const float4* __restrict__ pred4,  // [N/2] float4 (2 rows each)
                const float4* __restrict__ gold4,  // [N/4] float4
                int n8,                            // N/8
                float* __restrict__ out,
                unsigned int nblocks)
{
    int i = blockIdx.x * blockDim.x + threadIdx.x;   // < 2^21 for N=2^24
    float acc0 = 0.0f, acc1 = 0.0f;
    if (i < n8) {
        // batch all 6 loads up front (MLP=6)
        float4 ga = gold4[2 * i];
        float4 gb = gold4[2 * i + 1];
        float4 pa = pred4[4 * i];
        float4 pb = pred4[4 * i + 1];
        float4 pc = pred4[4 * i + 2];
        float4 pd = pred4[4 * i + 3];
        acc0  = row_loss(pa.x, pa.y, ga.x);
        acc1  = row_loss(pa.z, pa.w, ga.y);
        acc0 += row_loss(pb.x, pb.y, ga.z);
        acc1 += row_loss(pb.z, pb.w, ga.w);
        acc0 += row_loss(pc.x, pc.y, gb.x);
        acc1 += row_loss(pc.z, pc.w, gb.y);
        acc0 += row_loss(pd.x, pd.y, gb.z);
        acc1 += row_loss(pd.z, pd.w, gb.w);
    }
    float acc = acc0 + acc1;

    // warp reduce
    #pragma unroll
    for (int off = 16; off > 0; off >>= 1)
        acc += __shfl_down_sync(0xFFFFFFFFu, acc, off);

    __shared__ float warp_sums[8];
    int lane = threadIdx.x & 31;
    int wid  = threadIdx.x >> 5;
    if (lane == 0) warp_sums[wid] = acc;
    __syncthreads();

    if (wid == 0) {
        float v = (lane < 8) ? warp_sums[lane] : 0.0f;
        #pragma unroll
        for (int off = 4; off > 0; off >>= 1)
            v += __shfl_down_sync(0xFFFFFFFFu, v, off);

        if (lane == 0) {
            atomicAdd(&g_acc, (double)v);
            __threadfence();
            unsigned int prev = atomicAdd(&g_done, 1u);
            if (prev == nblocks - 1u) {
                out[0] = (float)g_acc;   // CORR = 1.0
                g_acc  = 0.0;            // reset for next graph replay
                g_done = 0u;
                __threadfence();
            }
        }
    }
}

// Leftover rows (n % 8) — only launched when needed (never for N = 2^24).
// Runs BEFORE the main kernel so its contribution is in g_acc when the
// last block finalizes. Adds into g_acc directly.
__global__ void fl_tail_kernel(const float* __restrict__ pred,
                               const float* __restrict__ gold,
                               int start, int n)
{
    if (threadIdx.x == 0) {
        float acc = 0.0f;
        for (int r = start; r < n; r++)
            acc += row_loss(pred[2 * r], pred[2 * r + 1], gold[r]);
        atomicAdd(&g_acc, (double)acc);
    }
}

extern "C" void kernel_launch(void* const* d_in, const int* in_sizes, int n_in,
                              void* d_out, int out_size)
{
    const float* pred = (const float*)d_in[0];
    const float* gold = (const float*)d_in[1];
    float* out = (float*)d_out;

    int n  = in_sizes[1];      // rows (gold element count)
    int n8 = n >> 3;

    int threads = 256;
    int blocks = (n8 + threads - 1) / threads;
    if (blocks < 1) blocks = 1;

    if (n & 7)
        fl_tail_kernel<<<1, 32>>>(pred, gold, n8 * 8, n);

    fl_fused_kernel<<<blocks, threads>>>(
        (const float4*)pred, (const float4*)gold, n8, out, (unsigned)blocks);
}